// round 15
// baseline (speedup 1.0000x reference)
#include <cuda_runtime.h>

// Fixed shapes
#define N_TOK 4096          // B*S
#define DIM   1024
#define NE    8
#define CAP   1280
#define NEC   ((size_t)N_TOK * NE * CAP)   // 41,943,040 floats
#define ECD   ((size_t)NE * CAP * DIM)     // 10,485,760 floats

#define ROW     (NE * CAP)                 // 10240 floats per token row
#define ROW_F4  (ROW / 4)                  // 2560

#define LB      512                        // logits blocks in K1 (warp per token)
#define ZB1     2048                       // mask-zero blocks in K1
#define ZITER   20                         // f4/thread: 2048*256*20 = NEC/4 (mask only)

#define NSLOT   (NE * CAP)                 // 10240
#define SWEEPB  640                        // slot-sweep blocks (16 slots each)
#define K3GRID  (N_TOK + SWEEPB)

// Scratch (device globals; fully rewritten every replay -> graph-deterministic)
__device__ int      g_top[2][N_TOK];
__device__ float    g_prob[2][N_TOK];
__device__ int      g_slot_token[NSLOT];
__device__ unsigned g_tok_off[2][N_TOK];   // global slot e*CAP+r; 0xFFFFFFFF = dropped
__device__ float    g_tok_val[2][N_TOK];

// ---------------------------------------------------------------------------
// K1: blocks [0,LB)      = router logits (warp/token, w staged in smem)
//     blocks [LB,LB+ZB1) = zero the MASK region (167 MB streaming)
// (R9-proven: 31.3us measured)
// ---------------------------------------------------------------------------
__global__ void __launch_bounds__(256) k_main(const float* __restrict__ x,
                                              const float* __restrict__ w,
                                              float* __restrict__ out_m,
                                              float* __restrict__ logits_out) {
    if (blockIdx.x >= LB) {
        float4* dst = (float4*)out_m;
        unsigned t0 = (blockIdx.x - LB) * 256 + threadIdx.x;
        const unsigned stride = ZB1 * 256;
        const float4 z = make_float4(0.f, 0.f, 0.f, 0.f);
#pragma unroll
        for (int k = 0; k < ZITER; k++)
            __stcs(&dst[t0 + (size_t)k * stride], z);
        return;
    }

    __shared__ float4 ws4[NE * (DIM / 4)];   // 32 KB
    const int tid = threadIdx.x;
    const float4* w4 = (const float4*)w;
    for (int i = tid; i < NE * (DIM / 4); i += 256) ws4[i] = w4[i];
    __syncthreads();

    const int warp = tid >> 5, lane = tid & 31;
    const int n = blockIdx.x * 8 + warp;

    const float4* xr = (const float4*)(x + (size_t)n * DIM);
    float acc[NE];
#pragma unroll
    for (int e = 0; e < NE; e++) acc[e] = 0.f;

#pragma unroll
    for (int ii = 0; ii < (DIM / 4) / 32; ii++) {   // 8 iterations
        int i = lane + ii * 32;
        float4 xv = xr[i];
#pragma unroll
        for (int e = 0; e < NE; e++) {
            float4 wv = ws4[e * (DIM / 4) + i];
            acc[e] = fmaf(xv.x, wv.x, acc[e]);
            acc[e] = fmaf(xv.y, wv.y, acc[e]);
            acc[e] = fmaf(xv.z, wv.z, acc[e]);
            acc[e] = fmaf(xv.w, wv.w, acc[e]);
        }
    }
#pragma unroll
    for (int e = 0; e < NE; e++) {
#pragma unroll
        for (int o = 16; o > 0; o >>= 1)
            acc[e] += __shfl_down_sync(0xffffffffu, acc[e], o);
    }

    if (lane == 0) {
        // top-2, jax.lax.top_k tie-break (lowest index wins)
        int i0 = 0; float v0 = acc[0];
#pragma unroll
        for (int e = 1; e < NE; e++) if (acc[e] > v0) { v0 = acc[e]; i0 = e; }
        int i1 = -1; float v1 = -INFINITY;
#pragma unroll
        for (int e = 0; e < NE; e++)
            if (e != i0 && acc[e] > v1) { v1 = acc[e]; i1 = e; }
        float t   = expf(v1 - v0);          // <= 1
        float den = 1.f + t;
        g_top[0][n]  = i0;
        g_top[1][n]  = i1;
        g_prob[0][n] = 1.f / den;
        g_prob[1][n] = t / den;
#pragma unroll
        for (int e = 0; e < NE; e++) logits_out[(size_t)n * NE + e] = acc[e];
    }
}

// ---------------------------------------------------------------------------
// K2: ordered per-expert rank scan (k-major), 1 block 1024 thr x 8 items.
// Writes scratch (offsets/values, slot map) AND the mask nonzeros (mask
// region was zeroed by K1; kernel boundary orders the writes).
// ---------------------------------------------------------------------------
__global__ void __launch_bounds__(1024) k_scan(float* __restrict__ out_m) {
    const int IPT = (2 * N_TOK) / 1024;   // 8
    const int tid  = threadIdx.x;
    const int lane = tid & 31, warp = tid >> 5;

    for (int i = tid; i < NSLOT; i += 1024) g_slot_token[i] = -1;
    __syncthreads();

    int cnt[NE];
#pragma unroll
    for (int e = 0; e < NE; e++) cnt[e] = 0;
    int ex[IPT];
    const int j0 = tid * IPT;
#pragma unroll
    for (int i = 0; i < IPT; i++) {
        int j = j0 + i;
        int k = (j >= N_TOK) ? 1 : 0;
        int n = j - k * N_TOK;
        int e = g_top[k][n];
        ex[i] = e;
        cnt[e]++;
    }

    int incl[NE];
#pragma unroll
    for (int e = 0; e < NE; e++) {
        int v = cnt[e];
#pragma unroll
        for (int o = 1; o < 32; o <<= 1) {
            int u = __shfl_up_sync(0xffffffffu, v, o);
            if (lane >= o) v += u;
        }
        incl[e] = v;
    }

    __shared__ int wtot[32][NE];
    __shared__ int wbase[32][NE];
    if (lane == 31) {
#pragma unroll
        for (int e = 0; e < NE; e++) wtot[warp][e] = incl[e];
    }
    __syncthreads();
    if (warp == 0) {
#pragma unroll
        for (int e = 0; e < NE; e++) {
            int v = wtot[lane][e];
            int iv = v;
#pragma unroll
            for (int o = 1; o < 32; o <<= 1) {
                int u = __shfl_up_sync(0xffffffffu, iv, o);
                if (lane >= o) iv += u;
            }
            wbase[lane][e] = iv - v;
        }
    }
    __syncthreads();

    int base[NE];
#pragma unroll
    for (int e = 0; e < NE; e++) base[e] = wbase[warp][e] + incl[e] - cnt[e];

#pragma unroll
    for (int i = 0; i < IPT; i++) {
        int j = j0 + i;
        int k = (j >= N_TOK) ? 1 : 0;
        int n = j - k * N_TOK;
        int e = ex[i];
        int r = base[e]++;
        float p = g_prob[k][n];
        unsigned off = 0xFFFFFFFFu;
        if (r < CAP && p > 0.f) {
            off = (unsigned)(e * CAP + r);
            g_slot_token[off] = n;
            out_m[(size_t)n * ROW + off] = 1.0f;   // mask patch (zeroed in K1)
        }
        g_tok_off[k][n] = off;
        g_tok_val[k][n] = p;
    }
}

// ---------------------------------------------------------------------------
// K3: blocks [0,N_TOK):  token blocks — zero the token's WEIGHT row with
//                        inline w-patch, and PUSH the token's x row to its
//                        <=2 batch slots (write-once; injective slot map).
//     blocks [N_TOK, +SWEEPB): sweep 16 slots each — zero only EMPTY slots.
// ---------------------------------------------------------------------------
__global__ void __launch_bounds__(256) k_finish(const float* __restrict__ x,
                                                float* __restrict__ out_w,
                                                float* __restrict__ out_b) {
    const int t = threadIdx.x;

    if (blockIdx.x < N_TOK) {
        const int n = blockIdx.x;
        const unsigned off0 = g_tok_off[0][n], off1 = g_tok_off[1][n];
        const float    p0   = g_tok_val[0][n], p1   = g_tok_val[1][n];
        const unsigned f0 = off0 >> 2, c0 = off0 & 3;
        const unsigned f1 = off1 >> 2, c1 = off1 & 3;

        // early coalesced x-row read (overlaps the zero stores below)
        const float4 xv = __ldg(&((const float4*)(x + (size_t)n * DIM))[t]);

        float4* dw = (float4*)out_w + (size_t)n * ROW_F4;
#pragma unroll
        for (int k = 0; k < ROW_F4 / 256; k++) {   // 10 iterations
            unsigned f = k * 256 + t;
            float4 zw = make_float4(0.f, 0.f, 0.f, 0.f);
            if (f == f0) {
                if (c0 == 0) zw.x = p0; else if (c0 == 1) zw.y = p0;
                else if (c0 == 2) zw.z = p0; else zw.w = p0;
            }
            if (f == f1) {
                if (c1 == 0) zw.x = p1; else if (c1 == 1) zw.y = p1;
                else if (c1 == 2) zw.z = p1; else zw.w = p1;
            }
            __stcs(&dw[f], zw);
        }

        if (off0 != 0xFFFFFFFFu)
            __stcs(&((float4*)(out_b + (size_t)off0 * DIM))[t], xv);
        if (off1 != 0xFFFFFFFFu)
            __stcs(&((float4*)(out_b + (size_t)off1 * DIM))[t], xv);
        return;
    }

    // ---- sweep blocks: zero empty batch slots ----
    const int s0 = (blockIdx.x - N_TOK) * 16;
    const float4 z = make_float4(0.f, 0.f, 0.f, 0.f);
#pragma unroll
    for (int j = 0; j < 16; j++) {
        if (g_slot_token[s0 + j] < 0)
            __stcs(&((float4*)(out_b + (size_t)(s0 + j) * DIM))[t], z);
    }
}

// ---------------------------------------------------------------------------
extern "C" void kernel_launch(void* const* d_in, const int* in_sizes, int n_in,
                              void* d_out, int out_size) {
    const float* x = (const float*)d_in[0];
    const float* w = (const float*)d_in[1];
    if (in_sizes[0] == NE * DIM && in_sizes[1] == N_TOK * DIM) {
        const float* tmp = x; x = w; w = tmp;
    }

    float* out   = (float*)d_out;          // [N,E,cap] w | [N,E,cap] m | [E,cap,D] b | [B,S,E] l
    float* out_w = out;
    float* out_m = out + NEC;
    float* out_b = out + 2 * NEC;
    float* out_l = out + 2 * NEC + ECD;

    k_main<<<LB + ZB1, 256>>>(x, w, out_m, out_l);   // logits + zero mask region
    k_scan<<<1, 1024>>>(out_m);
    k_finish<<<K3GRID, 256>>>(x, out_w, out_b);
}

// round 16
// speedup vs baseline: 1.0717x; 1.0717x over previous
#include <cuda_runtime.h>

// Fixed shapes
#define N_TOK 4096          // B*S
#define DIM   1024
#define NE    8
#define CAP   1280
#define NEC   ((size_t)N_TOK * NE * CAP)   // 41,943,040 floats
#define ECD   ((size_t)NE * CAP * DIM)     // 10,485,760 floats

#define ROW     (NE * CAP)                 // 10240 floats per token row
#define ROW_F4  (ROW / 4)                  // 2560

#define LB      512                        // logits blocks in K1 (warp per token)
#define ZB1     2560                       // zero blocks in K1
#define ZITER   20                         // f4/thread: 2560*256*20 = (NEC+ECD)/4 (mask+batches)

#define NSLOT   (NE * CAP)                 // 10240

// Scratch (device globals; fully rewritten every replay -> graph-deterministic)
__device__ int      g_top[2][N_TOK];
__device__ float    g_prob[2][N_TOK];
__device__ unsigned g_tok_off[2][N_TOK];   // global slot e*CAP+r; 0xFFFFFFFF = dropped
__device__ float    g_tok_val[2][N_TOK];

// ---------------------------------------------------------------------------
// K1: blocks [0,LB)      = router logits (warp/token, w staged in smem)
//     blocks [LB,LB+ZB1) = zero MASK + BATCHES regions (209 MB contiguous)
// (R9-proven logits path; streaming majority hides the logits latency)
// ---------------------------------------------------------------------------
__global__ void __launch_bounds__(256) k_main(const float* __restrict__ x,
                                              const float* __restrict__ w,
                                              float* __restrict__ zero_base,  // = out + NEC
                                              float* __restrict__ logits_out) {
    if (blockIdx.x >= LB) {
        float4* dst = (float4*)zero_base;
        unsigned t0 = (blockIdx.x - LB) * 256 + threadIdx.x;
        const unsigned stride = ZB1 * 256;
        const float4 z = make_float4(0.f, 0.f, 0.f, 0.f);
#pragma unroll
        for (int k = 0; k < ZITER; k++)
            __stcs(&dst[t0 + (size_t)k * stride], z);
        return;
    }

    __shared__ float4 ws4[NE * (DIM / 4)];   // 32 KB
    const int tid = threadIdx.x;
    const float4* w4 = (const float4*)w;
    for (int i = tid; i < NE * (DIM / 4); i += 256) ws4[i] = w4[i];
    __syncthreads();

    const int warp = tid >> 5, lane = tid & 31;
    const int n = blockIdx.x * 8 + warp;

    const float4* xr = (const float4*)(x + (size_t)n * DIM);
    float acc[NE];
#pragma unroll
    for (int e = 0; e < NE; e++) acc[e] = 0.f;

#pragma unroll
    for (int ii = 0; ii < (DIM / 4) / 32; ii++) {   // 8 iterations
        int i = lane + ii * 32;
        float4 xv = xr[i];
#pragma unroll
        for (int e = 0; e < NE; e++) {
            float4 wv = ws4[e * (DIM / 4) + i];
            acc[e] = fmaf(xv.x, wv.x, acc[e]);
            acc[e] = fmaf(xv.y, wv.y, acc[e]);
            acc[e] = fmaf(xv.z, wv.z, acc[e]);
            acc[e] = fmaf(xv.w, wv.w, acc[e]);
        }
    }
#pragma unroll
    for (int e = 0; e < NE; e++) {
#pragma unroll
        for (int o = 16; o > 0; o >>= 1)
            acc[e] += __shfl_down_sync(0xffffffffu, acc[e], o);
    }

    if (lane == 0) {
        // top-2, jax.lax.top_k tie-break (lowest index wins)
        int i0 = 0; float v0 = acc[0];
#pragma unroll
        for (int e = 1; e < NE; e++) if (acc[e] > v0) { v0 = acc[e]; i0 = e; }
        int i1 = -1; float v1 = -INFINITY;
#pragma unroll
        for (int e = 0; e < NE; e++)
            if (e != i0 && acc[e] > v1) { v1 = acc[e]; i1 = e; }
        float t   = expf(v1 - v0);          // <= 1
        float den = 1.f + t;
        g_top[0][n]  = i0;
        g_top[1][n]  = i1;
        g_prob[0][n] = 1.f / den;
        g_prob[1][n] = t / den;
#pragma unroll
        for (int e = 0; e < NE; e++) logits_out[(size_t)n * NE + e] = acc[e];
    }
}

// ---------------------------------------------------------------------------
// K2: ordered per-expert rank scan (k-major). 1 block, 1024 thr x 8 items.
// Scratch only: per-token slot offsets/values. No output writes.
// ---------------------------------------------------------------------------
__global__ void __launch_bounds__(1024) k_scan() {
    const int IPT = (2 * N_TOK) / 1024;   // 8
    const int tid  = threadIdx.x;
    const int lane = tid & 31, warp = tid >> 5;

    int cnt[NE];
#pragma unroll
    for (int e = 0; e < NE; e++) cnt[e] = 0;
    int ex[IPT];
    const int j0 = tid * IPT;
#pragma unroll
    for (int i = 0; i < IPT; i++) {
        int j = j0 + i;
        int k = (j >= N_TOK) ? 1 : 0;
        int n = j - k * N_TOK;
        int e = g_top[k][n];
        ex[i] = e;
        cnt[e]++;
    }

    int incl[NE];
#pragma unroll
    for (int e = 0; e < NE; e++) {
        int v = cnt[e];
#pragma unroll
        for (int o = 1; o < 32; o <<= 1) {
            int u = __shfl_up_sync(0xffffffffu, v, o);
            if (lane >= o) v += u;
        }
        incl[e] = v;
    }

    __shared__ int wtot[32][NE];
    __shared__ int wbase[32][NE];
    if (lane == 31) {
#pragma unroll
        for (int e = 0; e < NE; e++) wtot[warp][e] = incl[e];
    }
    __syncthreads();
    if (warp == 0) {
#pragma unroll
        for (int e = 0; e < NE; e++) {
            int v = wtot[lane][e];
            int iv = v;
#pragma unroll
            for (int o = 1; o < 32; o <<= 1) {
                int u = __shfl_up_sync(0xffffffffu, iv, o);
                if (lane >= o) iv += u;
            }
            wbase[lane][e] = iv - v;
        }
    }
    __syncthreads();

    int base[NE];
#pragma unroll
    for (int e = 0; e < NE; e++) base[e] = wbase[warp][e] + incl[e] - cnt[e];

#pragma unroll
    for (int i = 0; i < IPT; i++) {
        int j = j0 + i;
        int k = (j >= N_TOK) ? 1 : 0;
        int n = j - k * N_TOK;
        int e = ex[i];
        int r = base[e]++;
        float p = g_prob[k][n];
        unsigned off = 0xFFFFFFFFu;
        if (r < CAP && p > 0.f) off = (unsigned)(e * CAP + r);
        g_tok_off[k][n] = off;
        g_tok_val[k][n] = p;
    }
}

// ---------------------------------------------------------------------------
// K3 (R12-proven, 6.3 TB/s): one block per token, pure streaming majority:
//   - zero the token's WEIGHT row with inline w-patch (10 f4 iterations)
//   - patch <=2 mask scalars (mask zeroed in K1)
//   - PUSH the token's x row (coalesced 4KB read) to its <=2 batch slots
//     (batches zeroed in K1; slot assignment injective -> no races)
// ---------------------------------------------------------------------------
__global__ void __launch_bounds__(256) k_finish(const float* __restrict__ x,
                                                float* __restrict__ out_w,
                                                float* __restrict__ out_m,
                                                float* __restrict__ out_b) {
    const int t = threadIdx.x;
    const int n = blockIdx.x;

    const unsigned off0 = g_tok_off[0][n], off1 = g_tok_off[1][n];
    const float    p0   = g_tok_val[0][n], p1   = g_tok_val[1][n];
    const unsigned f0 = off0 >> 2, c0 = off0 & 3;
    const unsigned f1 = off1 >> 2, c1 = off1 & 3;

    // x row read (coalesced) issued early to overlap with zero stores
    const float4 xv = __ldg(&((const float4*)(x + (size_t)n * DIM))[t]);

    float4* dw = (float4*)out_w + (size_t)n * ROW_F4;
#pragma unroll
    for (int k = 0; k < ROW_F4 / 256; k++) {   // 10 iterations
        unsigned f = k * 256 + t;
        float4 zw = make_float4(0.f, 0.f, 0.f, 0.f);
        if (f == f0) {
            if (c0 == 0) zw.x = p0; else if (c0 == 1) zw.y = p0;
            else if (c0 == 2) zw.z = p0; else zw.w = p0;
        }
        if (f == f1) {
            if (c1 == 0) zw.x = p1; else if (c1 == 1) zw.y = p1;
            else if (c1 == 2) zw.z = p1; else zw.w = p1;
        }
        __stcs(&dw[f], zw);
    }

    // mask patches (region zeroed by K1)
    if (t == 0 && off0 != 0xFFFFFFFFu) out_m[(size_t)n * ROW + off0] = 1.0f;
    if (t == 1 && off1 != 0xFFFFFFFFu) out_m[(size_t)n * ROW + off1] = 1.0f;

    // push to batch slots (write-once; empty slots remain zero from K1)
    if (off0 != 0xFFFFFFFFu)
        __stcs(&((float4*)(out_b + (size_t)off0 * DIM))[t], xv);
    if (off1 != 0xFFFFFFFFu)
        __stcs(&((float4*)(out_b + (size_t)off1 * DIM))[t], xv);
}

// ---------------------------------------------------------------------------
extern "C" void kernel_launch(void* const* d_in, const int* in_sizes, int n_in,
                              void* d_out, int out_size) {
    const float* x = (const float*)d_in[0];
    const float* w = (const float*)d_in[1];
    if (in_sizes[0] == NE * DIM && in_sizes[1] == N_TOK * DIM) {
        const float* tmp = x; x = w; w = tmp;
    }

    float* out   = (float*)d_out;          // [N,E,cap] w | [N,E,cap] m | [E,cap,D] b | [B,S,E] l
    float* out_w = out;
    float* out_m = out + NEC;
    float* out_b = out + 2 * NEC;
    float* out_l = out + 2 * NEC + ECD;

    k_main<<<LB + ZB1, 256>>>(x, w, out_m, out_l);   // logits + zero mask+batches
    k_scan<<<1, 1024>>>();
    k_finish<<<N_TOK, 256>>>(x, out_w, out_m, out_b);
}